// round 13
// baseline (speedup 1.0000x reference)
#include <cuda_runtime.h>
#include <cuda_fp16.h>
#include <math.h>
#include <stdint.h>

// Problem constants
#define BATCH 4
#define SEQ   2048
#define DIM   1024
#define NHEAD 16
#define HDIM  64
#define MLPD  4096
#define MTOK  (BATCH*SEQ)   // 8192 tokens

// -------- scratch (device globals; no allocation allowed) --------
__device__ __align__(16) __half g_h  [(size_t)MTOK * DIM];
__device__ __align__(16) __half g_qkv[(size_t)MTOK * 3 * DIM];
__device__ __align__(16) __half g_o  [(size_t)MTOK * DIM];
__device__ __align__(16) __half g_m1 [(size_t)MTOK * MLPD];
// pair-interleaved half weights: Wp[k/2][n] = (w[2k][n], w[2k+1][n])
__device__ __align__(16) __half2 g_qkvwP [(size_t)(DIM/2) * 3 * DIM];
__device__ __align__(16) __half2 g_projwP[(size_t)(DIM/2) * DIM];
__device__ __align__(16) __half2 g_fc1wP [(size_t)(DIM/2) * MLPD];
__device__ __align__(16) __half2 g_fc2wP [(size_t)(MLPD/2) * DIM];

// ---------------------------------------------------------------
// helpers
// ---------------------------------------------------------------
__device__ __forceinline__ uint32_t h2_bits(__half2 h) {
    return *reinterpret_cast<uint32_t*>(&h);
}
__device__ __forceinline__ void mma_f16(
    float& d0, float& d1, float& d2, float& d3,
    uint32_t a0, uint32_t a1, uint32_t a2, uint32_t a3,
    uint32_t b0, uint32_t b1)
{
    asm volatile(
        "mma.sync.aligned.m16n8k16.row.col.f32.f16.f16.f32 "
        "{%0,%1,%2,%3}, {%4,%5,%6,%7}, {%8,%9}, {%0,%1,%2,%3};\n"
        : "+f"(d0), "+f"(d1), "+f"(d2), "+f"(d3)
        : "r"(a0), "r"(a1), "r"(a2), "r"(a3), "r"(b0), "r"(b1));
}
__device__ __forceinline__ void cp16(uint32_t smem_dst, const void* gsrc) {
    asm volatile("cp.async.cg.shared.global [%0], [%1], 16;\n"
                 :: "r"(smem_dst), "l"(gsrc));
}
__device__ __forceinline__ void cp_commit() {
    asm volatile("cp.async.commit_group;\n");
}
__device__ __forceinline__ void cp_wait1() {
    asm volatile("cp.async.wait_group 1;\n");
}

// ---------------------------------------------------------------
// Weight convert: fp32 W[K][N] -> half2 pair-interleaved Wp[k2][n]
// ---------------------------------------------------------------
__global__ __launch_bounds__(256) void convw_kernel(
    const float* __restrict__ in, __half2* __restrict__ out, int N)
{
    int n  = blockIdx.x * 256 + threadIdx.x;
    int k2 = blockIdx.y;
    float a = in[(size_t)(2 * k2) * N + n];
    float b = in[(size_t)(2 * k2 + 1) * N + n];
    out[(size_t)k2 * N + n] = __floats2half2_rn(a, b);
}

// ---------------------------------------------------------------
// RMSNorm: fp32 in -> half out
// ---------------------------------------------------------------
__global__ __launch_bounds__(256) void rmsnorm_kernel(
    const float* __restrict__ x, const float* __restrict__ w, __half* __restrict__ y)
{
    int row = blockIdx.x;
    const float4* xr = (const float4*)(x + (size_t)row * DIM);
    float4 v = xr[threadIdx.x];
    float ss = v.x*v.x + v.y*v.y + v.z*v.z + v.w*v.w;
    #pragma unroll
    for (int o = 16; o; o >>= 1) ss += __shfl_xor_sync(0xffffffffu, ss, o);
    __shared__ float red[8];
    if ((threadIdx.x & 31) == 0) red[threadIdx.x >> 5] = ss;
    __syncthreads();
    float tot = 0.f;
    #pragma unroll
    for (int i = 0; i < 8; ++i) tot += red[i];
    float inv = rsqrtf(tot * (1.0f / DIM) + 1e-6f);
    float4 wv = ((const float4*)w)[threadIdx.x];
    __half2 h0 = __floats2half2_rn(v.x * inv * wv.x, v.y * inv * wv.y);
    __half2 h1 = __floats2half2_rn(v.z * inv * wv.z, v.w * inv * wv.w);
    __half2* yo = (__half2*)(y + (size_t)row * DIM) + threadIdx.x * 2;
    yo[0] = h0; yo[1] = h1;
}

// ---------------------------------------------------------------
// FP16 mma GEMM (R12 winner, unchanged):
// Block 128x128, BK=32, 256 threads (8 warps 4x2), warp tile 32x64,
// 3-stage cp.async, scalar-LDS fragments, 2 CTAs/SM.
// ---------------------------------------------------------------
#define AP2 20            // A pitch in half2 (16 + 4 pad)
#define BP2 136           // B pitch in half2 (128 + 8 pad)
#define ASTG_B (128 * AP2 * 4)   // 10240 B per stage
#define BSTG_B (16 * BP2 * 4)    // 8704 B per stage
#define GSTAGES 3
#define GEMM_SMEM (GSTAGES * (ASTG_B + BSTG_B))   // 56832 B

template<bool OUT_HALF, bool HAS_BIAS, bool DO_SILU, bool HAS_RES>
__global__ __launch_bounds__(256, 2) void gemm16_kernel(
    const __half* __restrict__ A, const __half2* __restrict__ Bp,
    void* __restrict__ Cv, const float* __restrict__ bias,
    const float* __restrict__ res, int N, int K)
{
    extern __shared__ __align__(16) char dsm[];

    const int tid  = threadIdx.x;
    const int lane = tid & 31, warp = tid >> 5;
    const int wm = (warp & 3) * 32;
    const int wn = (warp >> 2) * 64;
    const int g  = lane >> 2, tig = lane & 3;
    const int rowBase = blockIdx.y * 128;
    const int colBase = blockIdx.x * 128;
    const uint32_t sbase = (uint32_t)__cvta_generic_to_shared(dsm);

    auto ldg = [&](int t, int buf) {
        int k0 = t << 5;
        uint32_t ab = sbase + buf * ASTG_B;
        #pragma unroll
        for (int it = 0; it < 2; ++it) {
            int cid = tid + it * 256;
            int row = cid >> 2, ch = cid & 3;
            cp16(ab + (row * AP2 + ch * 4) * 4,
                 A + (size_t)(rowBase + row) * K + k0 + ch * 8);
        }
        uint32_t bb = sbase + GSTAGES * ASTG_B + buf * BSTG_B;
        #pragma unroll
        for (int it = 0; it < 2; ++it) {
            int cid = tid + it * 256;
            int k2 = cid >> 5, nc = (cid & 31) * 4;
            cp16(bb + (k2 * BP2 + nc) * 4,
                 Bp + (size_t)((k0 >> 1) + k2) * N + colBase + nc);
        }
        cp_commit();
    };

    float acc[2][8][4];
    #pragma unroll
    for (int mt = 0; mt < 2; ++mt)
        #pragma unroll
        for (int nt = 0; nt < 8; ++nt)
            #pragma unroll
            for (int q = 0; q < 4; ++q) acc[mt][nt][q] = 0.f;

    auto compute = [&](int buf) {
        const uint32_t* Ab = (const uint32_t*)(dsm + buf * ASTG_B);
        const uint32_t* Bb = (const uint32_t*)(dsm + GSTAGES * ASTG_B + buf * BSTG_B);
        #pragma unroll
        for (int s = 0; s < 2; ++s) {
            const int kb2 = s * 8;
            uint32_t af[2][4];
            #pragma unroll
            for (int mt = 0; mt < 2; ++mt) {
                int r = wm + mt * 16 + g;
                af[mt][0] = Ab[ r      * AP2 + kb2 + tig];
                af[mt][1] = Ab[(r + 8) * AP2 + kb2 + tig];
                af[mt][2] = Ab[ r      * AP2 + kb2 + tig + 4];
                af[mt][3] = Ab[(r + 8) * AP2 + kb2 + tig + 4];
            }
            uint32_t bf[8][2];
            #pragma unroll
            for (int nt = 0; nt < 8; ++nt) {
                int c = wn + nt * 8 + g;
                bf[nt][0] = Bb[(kb2 + tig)     * BP2 + c];
                bf[nt][1] = Bb[(kb2 + tig + 4) * BP2 + c];
            }
            #pragma unroll
            for (int mt = 0; mt < 2; ++mt)
                #pragma unroll
                for (int nt = 0; nt < 8; ++nt)
                    mma_f16(acc[mt][nt][0], acc[mt][nt][1],
                            acc[mt][nt][2], acc[mt][nt][3],
                            af[mt][0], af[mt][1], af[mt][2], af[mt][3],
                            bf[nt][0], bf[nt][1]);
        }
    };

    const int nk = K >> 5;
    ldg(0, 0);
    ldg(1, 1);
    for (int t = 0; t < nk; ++t) {
        cp_wait1();
        __syncthreads();
        if (t + 2 < nk) ldg(t + 2, (t + 2) % GSTAGES);
        compute(t % GSTAGES);
    }

    // epilogue
    #pragma unroll
    for (int mt = 0; mt < 2; ++mt) {
        #pragma unroll
        for (int nt = 0; nt < 8; ++nt) {
            int r0 = rowBase + wm + mt * 16 + g;
            int r1 = r0 + 8;
            int c  = colBase + wn + nt * 8 + 2 * tig;
            float v0 = acc[mt][nt][0], v1 = acc[mt][nt][1];
            float v2 = acc[mt][nt][2], v3 = acc[mt][nt][3];
            if (HAS_BIAS) {
                float2 bv = *(const float2*)&bias[c];
                v0 += bv.x; v1 += bv.y; v2 += bv.x; v3 += bv.y;
            }
            if (DO_SILU) {
                v0 = v0 / (1.f + __expf(-v0));
                v1 = v1 / (1.f + __expf(-v1));
                v2 = v2 / (1.f + __expf(-v2));
                v3 = v3 / (1.f + __expf(-v3));
            }
            if (HAS_RES) {
                float2 rv0 = *(const float2*)&res[(size_t)r0 * N + c];
                float2 rv1 = *(const float2*)&res[(size_t)r1 * N + c];
                v0 += rv0.x; v1 += rv0.y; v2 += rv1.x; v3 += rv1.y;
            }
            if (OUT_HALF) {
                __half* C = (__half*)Cv;
                *(__half2*)(C + (size_t)r0 * N + c) = __floats2half2_rn(v0, v1);
                *(__half2*)(C + (size_t)r1 * N + c) = __floats2half2_rn(v2, v3);
            } else {
                float* C = (float*)Cv;
                float2 p0 = {v0, v1}, p1 = {v2, v3};
                *(float2*)(C + (size_t)r0 * N + c) = p0;
                *(float2*)(C + (size_t)r1 * N + c) = p1;
            }
        }
    }
}

// ---------------------------------------------------------------
// FP16 flash attention, v3: 2 CTAs/SM + K/V global-load prefetch.
// grid=(SEQ/128, NHEAD, BATCH), 256 threads.
// ---------------------------------------------------------------
#define QF2_SZ (16 * 264)
#define KVP 68
#define KPU_SZ (16 * KVP)
#define ATTN_SMEM ((2 * QF2_SZ) * 4 + (2 * KPU_SZ) * 8)   // 51200 B

__global__ __launch_bounds__(256, 2) void attn_kernel(
    const __half* __restrict__ qkv, __half* __restrict__ o)
{
    extern __shared__ __align__(16) uint32_t sm2[];
    uint32_t* Qf = sm2;
    uint32_t* Pf = Qf + QF2_SZ;
    uint2*    Kp = (uint2*)(Pf + QF2_SZ);
    uint2*    Vp = Kp + KPU_SZ;

    const int tid  = threadIdx.x;
    const int lane = tid & 31, warp = tid >> 5;
    const int g = lane >> 2, tig = lane & 3;

    const int qb = blockIdx.x, h = blockIdx.y, b = blockIdx.z;
    const size_t tokbase = (size_t)b * SEQ;
    const int qrow0 = qb * 128;
    const int qoff = h * HDIM;
    const int koff = DIM + h * HDIM;
    const int voff = 2 * DIM + h * HDIM;

    // per-thread staging coordinates
    const int kr  = tid >> 2;            // key 0..63 (K stage)
    const int kd0 = (tid & 3) * 16;      // 16 halfs
    const int vkp = tid & 31;            // key pair 0..31 (V stage)
    const int vd0 = (tid >> 5) * 8;      // 8 d values

    // ---- stage Q (A-frag pack) ----
    {
        int r  = tid >> 1;
        int d0 = (tid & 1) * 32;
        int w_ = r >> 4, g_ = r & 7, rb = (r >> 3) & 1;
        int posb = (w_ * 8 + g_) * 4 + rb;
        const __half* src = qkv + (tokbase + qrow0 + r) * (size_t)(3 * DIM) + qoff + d0;
        #pragma unroll
        for (int u = 0; u < 4; ++u) {
            uint4 ch = *(const uint4*)(src + u * 8);
            uint32_t w4[4] = {ch.x, ch.y, ch.z, ch.w};
            #pragma unroll
            for (int j = 0; j < 4; ++j) {
                int m = ((d0 + u * 8) >> 1) + j;
                int kb = m >> 3, mm = m & 7;
                int tg = mm & 3, slot = mm >> 2;
                Qf[(kb * 4 + tg) * 264 + posb + slot * 2] = w4[j];
            }
        }
    }

    float m_i[2], l_i[2], oa[8][4];
    m_i[0] = m_i[1] = -1e30f;
    l_i[0] = l_i[1] = 0.f;
    #pragma unroll
    for (int nt = 0; nt < 8; ++nt)
        #pragma unroll
        for (int q = 0; q < 4; ++q) oa[nt][q] = 0.f;

    const int wg4 = (warp * 8 + g) * 4;

    // prefetch registers for K (2x uint4) and V (2x uint4)
    uint4 kpre[2], vpre0, vpre1;
    auto load_tile = [&](int t) {
        const __half* ksrc = qkv + (tokbase + t * 64 + kr) * (size_t)(3 * DIM) + koff + kd0;
        kpre[0] = *(const uint4*)(ksrc);
        kpre[1] = *(const uint4*)(ksrc + 8);
        const __half* v0p = qkv + (tokbase + t * 64 + 2 * vkp)     * (size_t)(3 * DIM) + voff + vd0;
        const __half* v1p = qkv + (tokbase + t * 64 + 2 * vkp + 1) * (size_t)(3 * DIM) + voff + vd0;
        vpre0 = *(const uint4*)v0p;
        vpre1 = *(const uint4*)v1p;
    };

    load_tile(0);

    for (int t = 0; t < SEQ / 64; ++t) {
        __syncthreads();   // previous-iter readers of Kp/Vp done (covers Q stage at t=0)
        // ---- store prefetched K (pack) ----
        {
            uint32_t* Kpw = (uint32_t*)Kp;
            #pragma unroll
            for (int u = 0; u < 2; ++u) {
                uint32_t w4[4] = {kpre[u].x, kpre[u].y, kpre[u].z, kpre[u].w};
                #pragma unroll
                for (int j = 0; j < 4; ++j) {
                    int m = ((kd0 + u * 8) >> 1) + j;
                    int kb = m >> 3, mm = m & 7;
                    int tg = mm & 3, slot = mm >> 2;
                    Kpw[(((kb * 4 + tg) * KVP) + kr) * 2 + slot] = w4[j];
                }
            }
        }
        // ---- store prefetched V (pack, key-pair interleave) ----
        {
            int kb = vkp >> 3, mm = vkp & 7;
            int tg = mm & 3, slot = mm >> 2;
            uint32_t* Vpw = (uint32_t*)Vp;
            const __half2* h0 = (const __half2*)&vpre0;
            const __half2* h1 = (const __half2*)&vpre1;
            #pragma unroll
            for (int j = 0; j < 4; ++j) {
                __half2 lo = __halves2half2(__low2half(h0[j]),  __low2half(h1[j]));
                __half2 hi = __halves2half2(__high2half(h0[j]), __high2half(h1[j]));
                int d = vd0 + 2 * j;
                Vpw[(((kb * 4 + tg) * KVP) + d)     * 2 + slot] = h2_bits(lo);
                Vpw[(((kb * 4 + tg) * KVP) + d + 1) * 2 + slot] = h2_bits(hi);
            }
        }
        __syncthreads();

        // ---- prefetch next tile's K/V during compute ----
        if (t + 1 < SEQ / 64) load_tile(t + 1);

        // ---- S = Q @ K^T ----
        float s[8][4];
        #pragma unroll
        for (int nt = 0; nt < 8; ++nt)
            #pragma unroll
            for (int q = 0; q < 4; ++q) s[nt][q] = 0.f;
        #pragma unroll
        for (int kb = 0; kb < 4; ++kb) {
            uint4 aq = *(uint4*)&Qf[(kb * 4 + tig) * 264 + wg4];
            #pragma unroll
            for (int nt = 0; nt < 8; ++nt) {
                uint2 bv = Kp[(kb * 4 + tig) * KVP + nt * 8 + g];
                mma_f16(s[nt][0], s[nt][1], s[nt][2], s[nt][3],
                        aq.x, aq.y, aq.z, aq.w, bv.x, bv.y);
            }
        }

        // ---- online softmax ----
        const float scale = 0.125f;
        float mx0 = -1e30f, mx1 = -1e30f;
        #pragma unroll
        for (int nt = 0; nt < 8; ++nt) {
            s[nt][0] *= scale; s[nt][1] *= scale;
            s[nt][2] *= scale; s[nt][3] *= scale;
            mx0 = fmaxf(mx0, fmaxf(s[nt][0], s[nt][1]));
            mx1 = fmaxf(mx1, fmaxf(s[nt][2], s[nt][3]));
        }
        #pragma unroll
        for (int off = 1; off <= 2; off <<= 1) {
            mx0 = fmaxf(mx0, __shfl_xor_sync(0xffffffffu, mx0, off));
            mx1 = fmaxf(mx1, __shfl_xor_sync(0xffffffffu, mx1, off));
        }
        float mn0 = fmaxf(m_i[0], mx0), mn1 = fmaxf(m_i[1], mx1);
        float al0 = __expf(m_i[0] - mn0), al1 = __expf(m_i[1] - mn1);
        float rs0 = 0.f, rs1 = 0.f;
        #pragma unroll
        for (int nt = 0; nt < 8; ++nt) {
            s[nt][0] = __expf(s[nt][0] - mn0);
            s[nt][1] = __expf(s[nt][1] - mn0);
            s[nt][2] = __expf(s[nt][2] - mn1);
            s[nt][3] = __expf(s[nt][3] - mn1);
            rs0 += s[nt][0] + s[nt][1];
            rs1 += s[nt][2] + s[nt][3];
        }
        #pragma unroll
        for (int off = 1; off <= 2; off <<= 1) {
            rs0 += __shfl_xor_sync(0xffffffffu, rs0, off);
            rs1 += __shfl_xor_sync(0xffffffffu, rs1, off);
        }
        l_i[0] = l_i[0] * al0 + rs0;
        l_i[1] = l_i[1] * al1 + rs1;
        m_i[0] = mn0; m_i[1] = mn1;
        #pragma unroll
        for (int nt = 0; nt < 8; ++nt) {
            oa[nt][0] *= al0; oa[nt][1] *= al0;
            oa[nt][2] *= al1; oa[nt][3] *= al1;
        }

        // ---- stage P (A-frag pack, half; warp-private rows) ----
        #pragma unroll
        for (int nt = 0; nt < 8; ++nt) {
            int row = (nt >> 1) * 4 + tig;
            int off = wg4 + (nt & 1) * 2;
            __half2* p = (__half2*)&Pf[row * 264 + off];
            p[0] = __floats2half2_rn(s[nt][0], s[nt][1]);
            p[1] = __floats2half2_rn(s[nt][2], s[nt][3]);
        }
        __syncwarp();

        // ---- O += P @ V ----
        #pragma unroll
        for (int kb = 0; kb < 4; ++kb) {
            uint4 ap = *(uint4*)&Pf[(kb * 4 + tig) * 264 + wg4];
            #pragma unroll
            for (int nt = 0; nt < 8; ++nt) {
                uint2 bv = Vp[(kb * 4 + tig) * KVP + nt * 8 + g];
                mma_f16(oa[nt][0], oa[nt][1], oa[nt][2], oa[nt][3],
                        ap.x, ap.y, ap.z, ap.w, bv.x, bv.y);
            }
        }
        __syncwarp();
    }

    // ---- write O (half) ----
    float inv0 = 1.f / l_i[0], inv1 = 1.f / l_i[1];
    size_t tok0 = tokbase + qrow0 + warp * 16 + g;
    size_t tok1 = tok0 + 8;
    #pragma unroll
    for (int nt = 0; nt < 8; ++nt) {
        int c = qoff + nt * 8 + 2 * tig;
        *(__half2*)(o + tok0 * DIM + c) = __floats2half2_rn(oa[nt][0] * inv0, oa[nt][1] * inv0);
        *(__half2*)(o + tok1 * DIM + c) = __floats2half2_rn(oa[nt][2] * inv1, oa[nt][3] * inv1);
    }
}

// ---------------------------------------------------------------
extern "C" void kernel_launch(void* const* d_in, const int* in_sizes, int n_in,
                              void* d_out, int out_size)
{
    const float* x     = (const float*)d_in[0];
    const float* n1w   = (const float*)d_in[1];
    const float* qkvw  = (const float*)d_in[2];
    const float* projw = (const float*)d_in[3];
    const float* projb = (const float*)d_in[4];
    const float* n2w   = (const float*)d_in[5];
    const float* fc1w  = (const float*)d_in[6];
    const float* fc1b  = (const float*)d_in[7];
    const float* fc2w  = (const float*)d_in[8];
    const float* fc2b  = (const float*)d_in[9];
    float* out = (float*)d_out;

    __half *h, *qkv, *o, *m1;
    __half2 *qkvwP, *projwP, *fc1wP, *fc2wP;
    cudaGetSymbolAddress((void**)&h,      g_h);
    cudaGetSymbolAddress((void**)&qkv,    g_qkv);
    cudaGetSymbolAddress((void**)&o,      g_o);
    cudaGetSymbolAddress((void**)&m1,     g_m1);
    cudaGetSymbolAddress((void**)&qkvwP,  g_qkvwP);
    cudaGetSymbolAddress((void**)&projwP, g_projwP);
    cudaGetSymbolAddress((void**)&fc1wP,  g_fc1wP);
    cudaGetSymbolAddress((void**)&fc2wP,  g_fc2wP);

    static bool attr_done = false;
    if (!attr_done) {
        cudaFuncSetAttribute(gemm16_kernel<true, false, false, false>,
                             cudaFuncAttributeMaxDynamicSharedMemorySize, GEMM_SMEM);
        cudaFuncSetAttribute(gemm16_kernel<false, true, false, true>,
                             cudaFuncAttributeMaxDynamicSharedMemorySize, GEMM_SMEM);
        cudaFuncSetAttribute(gemm16_kernel<true, true, true, false>,
                             cudaFuncAttributeMaxDynamicSharedMemorySize, GEMM_SMEM);
        cudaFuncSetAttribute(attn_kernel,
                             cudaFuncAttributeMaxDynamicSharedMemorySize, ATTN_SMEM);
        attr_done = true;
    }

    // 0) convert weights to pair-interleaved half
    convw_kernel<<<dim3(3 * DIM / 256, DIM / 2), 256>>>(qkvw, qkvwP, 3 * DIM);
    convw_kernel<<<dim3(DIM / 256, DIM / 2),     256>>>(projw, projwP, DIM);
    convw_kernel<<<dim3(MLPD / 256, DIM / 2),    256>>>(fc1w, fc1wP, MLPD);
    convw_kernel<<<dim3(DIM / 256, MLPD / 2),    256>>>(fc2w, fc2wP, DIM);

    // 1) h = rmsnorm(x, norm1_w)  [half]
    rmsnorm_kernel<<<MTOK, 256>>>(x, n1w, h);
    // 2) qkv = h @ qkv_w  [half]
    gemm16_kernel<true, false, false, false>
        <<<dim3(3 * DIM / 128, MTOK / 128), 256, GEMM_SMEM>>>(
        h, qkvwP, qkv, nullptr, nullptr, 3 * DIM, DIM);
    // 3) attention -> o  [half]
    attn_kernel<<<dim3(SEQ / 128, NHEAD, BATCH), 256, ATTN_SMEM>>>(qkv, o);
    // 4) out = x + o @ proj_w + proj_b  [fp32]
    gemm16_kernel<false, true, false, true>
        <<<dim3(DIM / 128, MTOK / 128), 256, GEMM_SMEM>>>(
        o, projwP, out, projb, x, DIM, DIM);
    // 5) h = rmsnorm(out, norm2_w)  [half]
    rmsnorm_kernel<<<MTOK, 256>>>(out, n2w, h);
    // 6) m1 = silu(h @ fc1_w + fc1_b)  [half]
    gemm16_kernel<true, true, true, false>
        <<<dim3(MLPD / 128, MTOK / 128), 256, GEMM_SMEM>>>(
        h, fc1wP, m1, fc1b, nullptr, MLPD, DIM);
    // 7) out = out + m1 @ fc2_w + fc2_b  [fp32]
    gemm16_kernel<false, true, false, true>
        <<<dim3(DIM / 128, MTOK / 128), 256, GEMM_SMEM>>>(
        m1, fc2wP, out, fc2b, out, DIM, MLPD);
}

// round 15
// speedup vs baseline: 1.0400x; 1.0400x over previous
#include <cuda_runtime.h>
#include <cuda_fp16.h>
#include <math.h>
#include <stdint.h>

// Problem constants
#define BATCH 4
#define SEQ   2048
#define DIM   1024
#define NHEAD 16
#define HDIM  64
#define MLPD  4096
#define MTOK  (BATCH*SEQ)   // 8192 tokens

// -------- scratch (device globals; no allocation allowed) --------
__device__ __align__(16) __half g_h  [(size_t)MTOK * DIM];
__device__ __align__(16) __half g_qkv[(size_t)MTOK * 3 * DIM];
__device__ __align__(16) __half g_o  [(size_t)MTOK * DIM];
__device__ __align__(16) __half g_m1 [(size_t)MTOK * MLPD];
// pair-interleaved half weights: Wp[k/2][n] = (w[2k][n], w[2k+1][n])
__device__ __align__(16) __half2 g_qkvwP [(size_t)(DIM/2) * 3 * DIM];
__device__ __align__(16) __half2 g_projwP[(size_t)(DIM/2) * DIM];
__device__ __align__(16) __half2 g_fc1wP [(size_t)(DIM/2) * MLPD];
__device__ __align__(16) __half2 g_fc2wP [(size_t)(MLPD/2) * DIM];

// ---------------------------------------------------------------
// helpers
// ---------------------------------------------------------------
__device__ __forceinline__ uint32_t h2_bits(__half2 h) {
    return *reinterpret_cast<uint32_t*>(&h);
}
__device__ __forceinline__ void mma_f16(
    float& d0, float& d1, float& d2, float& d3,
    uint32_t a0, uint32_t a1, uint32_t a2, uint32_t a3,
    uint32_t b0, uint32_t b1)
{
    asm volatile(
        "mma.sync.aligned.m16n8k16.row.col.f32.f16.f16.f32 "
        "{%0,%1,%2,%3}, {%4,%5,%6,%7}, {%8,%9}, {%0,%1,%2,%3};\n"
        : "+f"(d0), "+f"(d1), "+f"(d2), "+f"(d3)
        : "r"(a0), "r"(a1), "r"(a2), "r"(a3), "r"(b0), "r"(b1));
}
__device__ __forceinline__ void cp16(uint32_t smem_dst, const void* gsrc) {
    asm volatile("cp.async.cg.shared.global [%0], [%1], 16;\n"
                 :: "r"(smem_dst), "l"(gsrc));
}
__device__ __forceinline__ void cp_commit() {
    asm volatile("cp.async.commit_group;\n");
}
__device__ __forceinline__ void cp_wait2() {
    asm volatile("cp.async.wait_group 2;\n");
}

// ---------------------------------------------------------------
// Weight convert: fp32 W[K][N] -> half2 pair-interleaved Wp[k2][n]
// ---------------------------------------------------------------
__global__ __launch_bounds__(256) void convw_kernel(
    const float* __restrict__ in, __half2* __restrict__ out, int N)
{
    int n  = blockIdx.x * 256 + threadIdx.x;
    int k2 = blockIdx.y;
    float a = in[(size_t)(2 * k2) * N + n];
    float b = in[(size_t)(2 * k2 + 1) * N + n];
    out[(size_t)k2 * N + n] = __floats2half2_rn(a, b);
}

// ---------------------------------------------------------------
// RMSNorm: fp32 in -> half out
// ---------------------------------------------------------------
__global__ __launch_bounds__(256) void rmsnorm_kernel(
    const float* __restrict__ x, const float* __restrict__ w, __half* __restrict__ y)
{
    int row = blockIdx.x;
    const float4* xr = (const float4*)(x + (size_t)row * DIM);
    float4 v = xr[threadIdx.x];
    float ss = v.x*v.x + v.y*v.y + v.z*v.z + v.w*v.w;
    #pragma unroll
    for (int o = 16; o; o >>= 1) ss += __shfl_xor_sync(0xffffffffu, ss, o);
    __shared__ float red[8];
    if ((threadIdx.x & 31) == 0) red[threadIdx.x >> 5] = ss;
    __syncthreads();
    float tot = 0.f;
    #pragma unroll
    for (int i = 0; i < 8; ++i) tot += red[i];
    float inv = rsqrtf(tot * (1.0f / DIM) + 1e-6f);
    float4 wv = ((const float4*)w)[threadIdx.x];
    __half2 h0 = __floats2half2_rn(v.x * inv * wv.x, v.y * inv * wv.y);
    __half2 h1 = __floats2half2_rn(v.z * inv * wv.z, v.w * inv * wv.w);
    __half2* yo = (__half2*)(y + (size_t)row * DIM) + threadIdx.x * 2;
    yo[0] = h0; yo[1] = h1;
}

// ---------------------------------------------------------------
// FP16 mma GEMM v5: Block 128x128, BK=32, 256 threads,
// warp grid 2x4 (warp tile 64x32), 4-stage cp.async, 2 CTAs/SM.
// ---------------------------------------------------------------
#define AP2 20            // A pitch in half2 (16 + 4 pad)
#define BP2 136           // B pitch in half2 (128 + 8 pad)
#define ASTG_B (128 * AP2 * 4)   // 10240 B per stage
#define BSTG_B (16 * BP2 * 4)    // 8704 B per stage
#define GSTAGES 4
#define GEMM_SMEM (GSTAGES * (ASTG_B + BSTG_B))   // 75776 B

template<bool OUT_HALF, bool HAS_BIAS, bool DO_SILU, bool HAS_RES>
__global__ __launch_bounds__(256, 2) void gemm16_kernel(
    const __half* __restrict__ A, const __half2* __restrict__ Bp,
    void* __restrict__ Cv, const float* __restrict__ bias,
    const float* __restrict__ res, int N, int K)
{
    extern __shared__ __align__(16) char dsm[];

    const int tid  = threadIdx.x;
    const int lane = tid & 31, warp = tid >> 5;
    const int wm = (warp & 1) * 64;        // 2 row-groups of 64
    const int wn = (warp >> 1) * 32;       // 4 col-groups of 32
    const int g  = lane >> 2, tig = lane & 3;
    const int rowBase = blockIdx.y * 128;
    const int colBase = blockIdx.x * 128;
    const uint32_t sbase = (uint32_t)__cvta_generic_to_shared(dsm);

    auto ldg = [&](int t, int buf) {
        int k0 = t << 5;
        uint32_t ab = sbase + buf * ASTG_B;
        #pragma unroll
        for (int it = 0; it < 2; ++it) {
            int cid = tid + it * 256;
            int row = cid >> 2, ch = cid & 3;
            cp16(ab + (row * AP2 + ch * 4) * 4,
                 A + (size_t)(rowBase + row) * K + k0 + ch * 8);
        }
        uint32_t bb = sbase + GSTAGES * ASTG_B + buf * BSTG_B;
        #pragma unroll
        for (int it = 0; it < 2; ++it) {
            int cid = tid + it * 256;
            int k2 = cid >> 5, nc = (cid & 31) * 4;
            cp16(bb + (k2 * BP2 + nc) * 4,
                 Bp + (size_t)((k0 >> 1) + k2) * N + colBase + nc);
        }
        cp_commit();
    };

    float acc[4][4][4];
    #pragma unroll
    for (int mt = 0; mt < 4; ++mt)
        #pragma unroll
        for (int nt = 0; nt < 4; ++nt)
            #pragma unroll
            for (int q = 0; q < 4; ++q) acc[mt][nt][q] = 0.f;

    auto compute = [&](int buf) {
        const uint32_t* Ab = (const uint32_t*)(dsm + buf * ASTG_B);
        const uint32_t* Bb = (const uint32_t*)(dsm + GSTAGES * ASTG_B + buf * BSTG_B);
        #pragma unroll
        for (int s = 0; s < 2; ++s) {
            const int kb2 = s * 8;
            uint32_t af[4][4];
            #pragma unroll
            for (int mt = 0; mt < 4; ++mt) {
                int r = wm + mt * 16 + g;
                af[mt][0] = Ab[ r      * AP2 + kb2 + tig];
                af[mt][1] = Ab[(r + 8) * AP2 + kb2 + tig];
                af[mt][2] = Ab[ r      * AP2 + kb2 + tig + 4];
                af[mt][3] = Ab[(r + 8) * AP2 + kb2 + tig + 4];
            }
            uint32_t bf[4][2];
            #pragma unroll
            for (int nt = 0; nt < 4; ++nt) {
                int c = wn + nt * 8 + g;
                bf[nt][0] = Bb[(kb2 + tig)     * BP2 + c];
                bf[nt][1] = Bb[(kb2 + tig + 4) * BP2 + c];
            }
            #pragma unroll
            for (int mt = 0; mt < 4; ++mt)
                #pragma unroll
                for (int nt = 0; nt < 4; ++nt)
                    mma_f16(acc[mt][nt][0], acc[mt][nt][1],
                            acc[mt][nt][2], acc[mt][nt][3],
                            af[mt][0], af[mt][1], af[mt][2], af[mt][3],
                            bf[nt][0], bf[nt][1]);
        }
    };

    const int nk = K >> 5;
    ldg(0, 0);
    ldg(1, 1);
    ldg(2, 2);
    for (int t = 0; t < nk; ++t) {
        cp_wait2();
        __syncthreads();
        if (t + 3 < nk) ldg(t + 3, (t + 3) & (GSTAGES - 1));
        compute(t & (GSTAGES - 1));
    }

    // epilogue
    #pragma unroll
    for (int mt = 0; mt < 4; ++mt) {
        #pragma unroll
        for (int nt = 0; nt < 4; ++nt) {
            int r0 = rowBase + wm + mt * 16 + g;
            int r1 = r0 + 8;
            int c  = colBase + wn + nt * 8 + 2 * tig;
            float v0 = acc[mt][nt][0], v1 = acc[mt][nt][1];
            float v2 = acc[mt][nt][2], v3 = acc[mt][nt][3];
            if (HAS_BIAS) {
                float2 bv = *(const float2*)&bias[c];
                v0 += bv.x; v1 += bv.y; v2 += bv.x; v3 += bv.y;
            }
            if (DO_SILU) {
                v0 = v0 / (1.f + __expf(-v0));
                v1 = v1 / (1.f + __expf(-v1));
                v2 = v2 / (1.f + __expf(-v2));
                v3 = v3 / (1.f + __expf(-v3));
            }
            if (HAS_RES) {
                float2 rv0 = *(const float2*)&res[(size_t)r0 * N + c];
                float2 rv1 = *(const float2*)&res[(size_t)r1 * N + c];
                v0 += rv0.x; v1 += rv0.y; v2 += rv1.x; v3 += rv1.y;
            }
            if (OUT_HALF) {
                __half* C = (__half*)Cv;
                *(__half2*)(C + (size_t)r0 * N + c) = __floats2half2_rn(v0, v1);
                *(__half2*)(C + (size_t)r1 * N + c) = __floats2half2_rn(v2, v3);
            } else {
                float* C = (float*)Cv;
                float2 p0 = {v0, v1}, p1 = {v2, v3};
                *(float2*)(C + (size_t)r0 * N + c) = p0;
                *(float2*)(C + (size_t)r1 * N + c) = p1;
            }
        }
    }
}

// ---------------------------------------------------------------
// FP16 flash attention (exact R12-passing version).
// grid=(SEQ/128, NHEAD, BATCH), 256 threads.
// ---------------------------------------------------------------
#define QF2_SZ (16 * 264)
#define KVP 68
#define KPU_SZ (16 * KVP)
#define ATTN_SMEM ((2 * QF2_SZ) * 4 + (2 * KPU_SZ) * 8)   // 51200 B

__global__ __launch_bounds__(256) void attn_kernel(
    const __half* __restrict__ qkv, __half* __restrict__ o)
{
    extern __shared__ __align__(16) uint32_t sm2[];
    uint32_t* Qf = sm2;
    uint32_t* Pf = Qf + QF2_SZ;
    uint2*    Kp = (uint2*)(Pf + QF2_SZ);
    uint2*    Vp = Kp + KPU_SZ;

    const int tid  = threadIdx.x;
    const int lane = tid & 31, warp = tid >> 5;
    const int g = lane >> 2, tig = lane & 3;

    const int qb = blockIdx.x, h = blockIdx.y, b = blockIdx.z;
    const size_t tokbase = (size_t)b * SEQ;
    const int qrow0 = qb * 128;
    const int qoff = h * HDIM;
    const int koff = DIM + h * HDIM;
    const int voff = 2 * DIM + h * HDIM;

    {
        int r  = tid >> 1;
        int d0 = (tid & 1) * 32;
        int w_ = r >> 4, g_ = r & 7, rb = (r >> 3) & 1;
        int posb = (w_ * 8 + g_) * 4 + rb;
        const __half* src = qkv + (tokbase + qrow0 + r) * (size_t)(3 * DIM) + qoff + d0;
        #pragma unroll
        for (int u = 0; u < 4; ++u) {
            uint4 ch = *(const uint4*)(src + u * 8);
            uint32_t w4[4] = {ch.x, ch.y, ch.z, ch.w};
            #pragma unroll
            for (int j = 0; j < 4; ++j) {
                int m = ((d0 + u * 8) >> 1) + j;
                int kb = m >> 3, mm = m & 7;
                int tg = mm & 3, slot = mm >> 2;
                Qf[(kb * 4 + tg) * 264 + posb + slot * 2] = w4[j];
            }
        }
    }

    float m_i[2], l_i[2], oa[8][4];
    m_i[0] = m_i[1] = -1e30f;
    l_i[0] = l_i[1] = 0.f;
    #pragma unroll
    for (int nt = 0; nt < 8; ++nt)
        #pragma unroll
        for (int q = 0; q < 4; ++q) oa[nt][q] = 0.f;

    const int wg4 = (warp * 8 + g) * 4;

    for (int t = 0; t < SEQ / 64; ++t) {
        __syncthreads();
        {
            int r  = tid >> 2;
            int d0 = (tid & 3) * 16;
            uint32_t* Kpw = (uint32_t*)Kp;
            const __half* ksrc = qkv + (tokbase + t * 64 + r) * (size_t)(3 * DIM) + koff + d0;
            #pragma unroll
            for (int u = 0; u < 2; ++u) {
                uint4 ch = *(const uint4*)(ksrc + u * 8);
                uint32_t w4[4] = {ch.x, ch.y, ch.z, ch.w};
                #pragma unroll
                for (int j = 0; j < 4; ++j) {
                    int m = ((d0 + u * 8) >> 1) + j;
                    int kb = m >> 3, mm = m & 7;
                    int tg = mm & 3, slot = mm >> 2;
                    Kpw[(((kb * 4 + tg) * KVP) + r) * 2 + slot] = w4[j];
                }
            }
        }
        {
            int kp = tid & 31;
            int d0 = (tid >> 5) * 8;
            int kb = kp >> 3, mm = kp & 7;
            int tg = mm & 3, slot = mm >> 2;
            uint32_t* Vpw = (uint32_t*)Vp;
            const __half* v0p = qkv + (tokbase + t * 64 + 2 * kp)     * (size_t)(3 * DIM) + voff + d0;
            const __half* v1p = qkv + (tokbase + t * 64 + 2 * kp + 1) * (size_t)(3 * DIM) + voff + d0;
            uint4 c0 = *(const uint4*)v0p;
            uint4 c1 = *(const uint4*)v1p;
            const __half2* h0 = (const __half2*)&c0;
            const __half2* h1 = (const __half2*)&c1;
            #pragma unroll
            for (int j = 0; j < 4; ++j) {
                __half2 lo = __halves2half2(__low2half(h0[j]),  __low2half(h1[j]));
                __half2 hi = __halves2half2(__high2half(h0[j]), __high2half(h1[j]));
                int d = d0 + 2 * j;
                Vpw[(((kb * 4 + tg) * KVP) + d)     * 2 + slot] = h2_bits(lo);
                Vpw[(((kb * 4 + tg) * KVP) + d + 1) * 2 + slot] = h2_bits(hi);
            }
        }
        __syncthreads();

        float s[8][4];
        #pragma unroll
        for (int nt = 0; nt < 8; ++nt)
            #pragma unroll
            for (int q = 0; q < 4; ++q) s[nt][q] = 0.f;
        #pragma unroll
        for (int kb = 0; kb < 4; ++kb) {
            uint4 aq = *(uint4*)&Qf[(kb * 4 + tig) * 264 + wg4];
            #pragma unroll
            for (int nt = 0; nt < 8; ++nt) {
                uint2 bv = Kp[(kb * 4 + tig) * KVP + nt * 8 + g];
                mma_f16(s[nt][0], s[nt][1], s[nt][2], s[nt][3],
                        aq.x, aq.y, aq.z, aq.w, bv.x, bv.y);
            }
        }

        const float scale = 0.125f;
        float mx0 = -1e30f, mx1 = -1e30f;
        #pragma unroll
        for (int nt = 0; nt < 8; ++nt) {
            s[nt][0] *= scale; s[nt][1] *= scale;
            s[nt][2] *= scale; s[nt][3] *= scale;
            mx0 = fmaxf(mx0, fmaxf(s[nt][0], s[nt][1]));
            mx1 = fmaxf(mx1, fmaxf(s[nt][2], s[nt][3]));
        }
        #pragma unroll
        for (int off = 1; off <= 2; off <<= 1) {
            mx0 = fmaxf(mx0, __shfl_xor_sync(0xffffffffu, mx0, off));
            mx1 = fmaxf(mx1, __shfl_xor_sync(0xffffffffu, mx1, off));
        }
        float mn0 = fmaxf(m_i[0], mx0), mn1 = fmaxf(m_i[1], mx1);
        float al0 = __expf(m_i[0] - mn0), al1 = __expf(m_i[1] - mn1);
        float rs0 = 0.f, rs1 = 0.f;
        #pragma unroll
        for (int nt = 0; nt < 8; ++nt) {
            s[nt][0] = __expf(s[nt][0] - mn0);
            s[nt][1] = __expf(s[nt][1] - mn0);
            s[nt][2] = __expf(s[nt][2] - mn1);
            s[nt][3] = __expf(s[nt][3] - mn1);
            rs0 += s[nt][0] + s[nt][1];
            rs1 += s[nt][2] + s[nt][3];
        }
        #pragma unroll
        for (int off = 1; off <= 2; off <<= 1) {
            rs0 += __shfl_xor_sync(0xffffffffu, rs0, off);
            rs1 += __shfl_xor_sync(0xffffffffu, rs1, off);
        }
        l_i[0] = l_i[0] * al0 + rs0;
        l_i[1] = l_i[1] * al1 + rs1;
        m_i[0] = mn0; m_i[1] = mn1;
        #pragma unroll
        for (int nt = 0; nt < 8; ++nt) {
            oa[nt][0] *= al0; oa[nt][1] *= al0;
            oa[nt][2] *= al1; oa[nt][3] *= al1;
        }

        #pragma unroll
        for (int nt = 0; nt < 8; ++nt) {
            int row = (nt >> 1) * 4 + tig;
            int off = wg4 + (nt & 1) * 2;
            __half2* p = (__half2*)&Pf[row * 264 + off];
            p[0] = __floats2half2_rn(s[nt][0], s[nt][1]);
            p[1] = __floats2half2_rn(s[nt][2], s[nt][3]);
        }
        __syncwarp();

        #pragma unroll
        for (int kb = 0; kb < 4; ++kb) {
            uint4 ap = *(uint4*)&Pf[(kb * 4 + tig) * 264 + wg4];
            #pragma unroll
            for (int nt = 0; nt < 8; ++nt) {
                uint2 bv = Vp[(kb * 4 + tig) * KVP + nt * 8 + g];
                mma_f16(oa[nt][0], oa[nt][1], oa[nt][2], oa[nt][3],
                        ap.x, ap.y, ap.z, ap.w, bv.x, bv.y);
            }
        }
        __syncwarp();
    }

    float inv0 = 1.f / l_i[0], inv1 = 1.f / l_i[1];
    size_t tok0 = tokbase + qrow0 + warp * 16 + g;
    size_t tok1 = tok0 + 8;
    #pragma unroll
    for (int nt = 0; nt < 8; ++nt) {
        int c = qoff + nt * 8 + 2 * tig;
        *(__half2*)(o + tok0 * DIM + c) = __floats2half2_rn(oa[nt][0] * inv0, oa[nt][1] * inv0);
        *(__half2*)(o + tok1 * DIM + c) = __floats2half2_rn(oa[nt][2] * inv1, oa[nt][3] * inv1);
    }
}

// ---------------------------------------------------------------
extern "C" void kernel_launch(void* const* d_in, const int* in_sizes, int n_in,
                              void* d_out, int out_size)
{
    const float* x     = (const float*)d_in[0];
    const float* n1w   = (const float*)d_in[1];
    const float* qkvw  = (const float*)d_in[2];
    const float* projw = (const float*)d_in[3];
    const float* projb = (const float*)d_in[4];
    const float* n2w   = (const float*)d_in[5];
    const float* fc1w  = (const float*)d_in[6];
    const float* fc1b  = (const float*)d_in[7];
    const float* fc2w  = (const float*)d_in[8];
    const float* fc2b  = (const float*)d_in[9];
    float* out = (float*)d_out;

    __half *h, *qkv, *o, *m1;
    __half2 *qkvwP, *projwP, *fc1wP, *fc2wP;
    cudaGetSymbolAddress((void**)&h,      g_h);
    cudaGetSymbolAddress((void**)&qkv,    g_qkv);
    cudaGetSymbolAddress((void**)&o,      g_o);
    cudaGetSymbolAddress((void**)&m1,     g_m1);
    cudaGetSymbolAddress((void**)&qkvwP,  g_qkvwP);
    cudaGetSymbolAddress((void**)&projwP, g_projwP);
    cudaGetSymbolAddress((void**)&fc1wP,  g_fc1wP);
    cudaGetSymbolAddress((void**)&fc2wP,  g_fc2wP);

    static bool attr_done = false;
    if (!attr_done) {
        cudaFuncSetAttribute(gemm16_kernel<true, false, false, false>,
                             cudaFuncAttributeMaxDynamicSharedMemorySize, GEMM_SMEM);
        cudaFuncSetAttribute(gemm16_kernel<false, true, false, true>,
                             cudaFuncAttributeMaxDynamicSharedMemorySize, GEMM_SMEM);
        cudaFuncSetAttribute(gemm16_kernel<true, true, true, false>,
                             cudaFuncAttributeMaxDynamicSharedMemorySize, GEMM_SMEM);
        cudaFuncSetAttribute(attn_kernel,
                             cudaFuncAttributeMaxDynamicSharedMemorySize, ATTN_SMEM);
        attr_done = true;
    }

    // 0) convert weights to pair-interleaved half
    convw_kernel<<<dim3(3 * DIM / 256, DIM / 2), 256>>>(qkvw, qkvwP, 3 * DIM);
    convw_kernel<<<dim3(DIM / 256, DIM / 2),     256>>>(projw, projwP, DIM);
    convw_kernel<<<dim3(MLPD / 256, DIM / 2),    256>>>(fc1w, fc1wP, MLPD);
    convw_kernel<<<dim3(DIM / 256, MLPD / 2),    256>>>(fc2w, fc2wP, DIM);

    // 1) h = rmsnorm(x, norm1_w)  [half]
    rmsnorm_kernel<<<MTOK, 256>>>(x, n1w, h);
    // 2) qkv = h @ qkv_w  [half]
    gemm16_kernel<true, false, false, false>
        <<<dim3(3 * DIM / 128, MTOK / 128), 256, GEMM_SMEM>>>(
        h, qkvwP, qkv, nullptr, nullptr, 3 * DIM, DIM);
    // 3) attention -> o  [half]
    attn_kernel<<<dim3(SEQ / 128, NHEAD, BATCH), 256, ATTN_SMEM>>>(qkv, o);
    // 4) out = x + o @ proj_w + proj_b  [fp32]
    gemm16_kernel<false, true, false, true>
        <<<dim3(DIM / 128, MTOK / 128), 256, GEMM_SMEM>>>(
        o, projwP, out, projb, x, DIM, DIM);
    // 5) h = rmsnorm(out, norm2_w)  [half]
    rmsnorm_kernel<<<MTOK, 256>>>(out, n2w, h);
    // 6) m1 = silu(h @ fc1_w + fc1_b)  [half]
    gemm16_kernel<true, true, true, false>
        <<<dim3(MLPD / 128, MTOK / 128), 256, GEMM_SMEM>>>(
        h, fc1wP, m1, fc1b, nullptr, MLPD, DIM);
    // 7) out = out + m1 @ fc2_w + fc2_b  [fp32]
    gemm16_kernel<false, true, false, true>
        <<<dim3(DIM / 128, MTOK / 128), 256, GEMM_SMEM>>>(
        m1, fc2wP, out, fc2b, out, DIM, MLPD);
}

// round 16
// speedup vs baseline: 1.0552x; 1.0146x over previous
#include <cuda_runtime.h>
#include <cuda_fp16.h>
#include <math.h>
#include <stdint.h>

// Problem constants
#define BATCH 4
#define SEQ   2048
#define DIM   1024
#define NHEAD 16
#define HDIM  64
#define MLPD  4096
#define MTOK  (BATCH*SEQ)   // 8192 tokens

// -------- scratch (device globals; no allocation allowed) --------
__device__ __align__(16) __half g_h  [(size_t)MTOK * DIM];
__device__ __align__(16) __half g_qkv[(size_t)MTOK * 3 * DIM];
__device__ __align__(16) __half g_o  [(size_t)MTOK * DIM];
__device__ __align__(16) __half g_m1 [(size_t)MTOK * MLPD];
// pair-interleaved half weights: Wp[k/2][n] = (w[2k][n], w[2k+1][n])
__device__ __align__(16) __half2 g_qkvwP [(size_t)(DIM/2) * 3 * DIM];
__device__ __align__(16) __half2 g_projwP[(size_t)(DIM/2) * DIM];
__device__ __align__(16) __half2 g_fc1wP [(size_t)(DIM/2) * MLPD];
__device__ __align__(16) __half2 g_fc2wP [(size_t)(MLPD/2) * DIM];

// ---------------------------------------------------------------
// helpers
// ---------------------------------------------------------------
__device__ __forceinline__ uint32_t h2_bits(__half2 h) {
    return *reinterpret_cast<uint32_t*>(&h);
}
__device__ __forceinline__ void mma_f16(
    float& d0, float& d1, float& d2, float& d3,
    uint32_t a0, uint32_t a1, uint32_t a2, uint32_t a3,
    uint32_t b0, uint32_t b1)
{
    asm volatile(
        "mma.sync.aligned.m16n8k16.row.col.f32.f16.f16.f32 "
        "{%0,%1,%2,%3}, {%4,%5,%6,%7}, {%8,%9}, {%0,%1,%2,%3};\n"
        : "+f"(d0), "+f"(d1), "+f"(d2), "+f"(d3)
        : "r"(a0), "r"(a1), "r"(a2), "r"(a3), "r"(b0), "r"(b1));
}
__device__ __forceinline__ void cp16(uint32_t smem_dst, const void* gsrc) {
    asm volatile("cp.async.cg.shared.global [%0], [%1], 16;\n"
                 :: "r"(smem_dst), "l"(gsrc));
}
__device__ __forceinline__ void cp_commit() {
    asm volatile("cp.async.commit_group;\n");
}
__device__ __forceinline__ void cp_wait2() {
    asm volatile("cp.async.wait_group 2;\n");
}

// ---------------------------------------------------------------
// Weight convert: fp32 W[K][N] -> half2 pair-interleaved Wp[k2][n]
// ---------------------------------------------------------------
__global__ __launch_bounds__(256) void convw_kernel(
    const float* __restrict__ in, __half2* __restrict__ out, int N)
{
    int n  = blockIdx.x * 256 + threadIdx.x;
    int k2 = blockIdx.y;
    float a = in[(size_t)(2 * k2) * N + n];
    float b = in[(size_t)(2 * k2 + 1) * N + n];
    out[(size_t)k2 * N + n] = __floats2half2_rn(a, b);
}

// ---------------------------------------------------------------
// RMSNorm: fp32 in -> half out
// ---------------------------------------------------------------
__global__ __launch_bounds__(256) void rmsnorm_kernel(
    const float* __restrict__ x, const float* __restrict__ w, __half* __restrict__ y)
{
    int row = blockIdx.x;
    const float4* xr = (const float4*)(x + (size_t)row * DIM);
    float4 v = xr[threadIdx.x];
    float ss = v.x*v.x + v.y*v.y + v.z*v.z + v.w*v.w;
    #pragma unroll
    for (int o = 16; o; o >>= 1) ss += __shfl_xor_sync(0xffffffffu, ss, o);
    __shared__ float red[8];
    if ((threadIdx.x & 31) == 0) red[threadIdx.x >> 5] = ss;
    __syncthreads();
    float tot = 0.f;
    #pragma unroll
    for (int i = 0; i < 8; ++i) tot += red[i];
    float inv = rsqrtf(tot * (1.0f / DIM) + 1e-6f);
    float4 wv = ((const float4*)w)[threadIdx.x];
    __half2 h0 = __floats2half2_rn(v.x * inv * wv.x, v.y * inv * wv.y);
    __half2 h1 = __floats2half2_rn(v.z * inv * wv.z, v.w * inv * wv.w);
    __half2* yo = (__half2*)(y + (size_t)row * DIM) + threadIdx.x * 2;
    yo[0] = h0; yo[1] = h1;
}

// ---------------------------------------------------------------
// FP16 mma GEMM (R15 winner, unchanged): Block 128x128, BK=32,
// 256 threads, warp grid 2x4 (warp tile 64x32), 4-stage cp.async,
// 2 CTAs/SM.
// ---------------------------------------------------------------
#define AP2 20            // A pitch in half2 (16 + 4 pad)
#define BP2 136           // B pitch in half2 (128 + 8 pad)
#define ASTG_B (128 * AP2 * 4)   // 10240 B per stage
#define BSTG_B (16 * BP2 * 4)    // 8704 B per stage
#define GSTAGES 4
#define GEMM_SMEM (GSTAGES * (ASTG_B + BSTG_B))   // 75776 B

template<bool OUT_HALF, bool HAS_BIAS, bool DO_SILU, bool HAS_RES>
__global__ __launch_bounds__(256, 2) void gemm16_kernel(
    const __half* __restrict__ A, const __half2* __restrict__ Bp,
    void* __restrict__ Cv, const float* __restrict__ bias,
    const float* __restrict__ res, int N, int K)
{
    extern __shared__ __align__(16) char dsm[];

    const int tid  = threadIdx.x;
    const int lane = tid & 31, warp = tid >> 5;
    const int wm = (warp & 1) * 64;        // 2 row-groups of 64
    const int wn = (warp >> 1) * 32;       // 4 col-groups of 32
    const int g  = lane >> 2, tig = lane & 3;
    const int rowBase = blockIdx.y * 128;
    const int colBase = blockIdx.x * 128;
    const uint32_t sbase = (uint32_t)__cvta_generic_to_shared(dsm);

    auto ldg = [&](int t, int buf) {
        int k0 = t << 5;
        uint32_t ab = sbase + buf * ASTG_B;
        #pragma unroll
        for (int it = 0; it < 2; ++it) {
            int cid = tid + it * 256;
            int row = cid >> 2, ch = cid & 3;
            cp16(ab + (row * AP2 + ch * 4) * 4,
                 A + (size_t)(rowBase + row) * K + k0 + ch * 8);
        }
        uint32_t bb = sbase + GSTAGES * ASTG_B + buf * BSTG_B;
        #pragma unroll
        for (int it = 0; it < 2; ++it) {
            int cid = tid + it * 256;
            int k2 = cid >> 5, nc = (cid & 31) * 4;
            cp16(bb + (k2 * BP2 + nc) * 4,
                 Bp + (size_t)((k0 >> 1) + k2) * N + colBase + nc);
        }
        cp_commit();
    };

    float acc[4][4][4];
    #pragma unroll
    for (int mt = 0; mt < 4; ++mt)
        #pragma unroll
        for (int nt = 0; nt < 4; ++nt)
            #pragma unroll
            for (int q = 0; q < 4; ++q) acc[mt][nt][q] = 0.f;

    auto compute = [&](int buf) {
        const uint32_t* Ab = (const uint32_t*)(dsm + buf * ASTG_B);
        const uint32_t* Bb = (const uint32_t*)(dsm + GSTAGES * ASTG_B + buf * BSTG_B);
        #pragma unroll
        for (int s = 0; s < 2; ++s) {
            const int kb2 = s * 8;
            uint32_t af[4][4];
            #pragma unroll
            for (int mt = 0; mt < 4; ++mt) {
                int r = wm + mt * 16 + g;
                af[mt][0] = Ab[ r      * AP2 + kb2 + tig];
                af[mt][1] = Ab[(r + 8) * AP2 + kb2 + tig];
                af[mt][2] = Ab[ r      * AP2 + kb2 + tig + 4];
                af[mt][3] = Ab[(r + 8) * AP2 + kb2 + tig + 4];
            }
            uint32_t bf[4][2];
            #pragma unroll
            for (int nt = 0; nt < 4; ++nt) {
                int c = wn + nt * 8 + g;
                bf[nt][0] = Bb[(kb2 + tig)     * BP2 + c];
                bf[nt][1] = Bb[(kb2 + tig + 4) * BP2 + c];
            }
            #pragma unroll
            for (int mt = 0; mt < 4; ++mt)
                #pragma unroll
                for (int nt = 0; nt < 4; ++nt)
                    mma_f16(acc[mt][nt][0], acc[mt][nt][1],
                            acc[mt][nt][2], acc[mt][nt][3],
                            af[mt][0], af[mt][1], af[mt][2], af[mt][3],
                            bf[nt][0], bf[nt][1]);
        }
    };

    const int nk = K >> 5;
    ldg(0, 0);
    ldg(1, 1);
    ldg(2, 2);
    for (int t = 0; t < nk; ++t) {
        cp_wait2();
        __syncthreads();
        if (t + 3 < nk) ldg(t + 3, (t + 3) & (GSTAGES - 1));
        compute(t & (GSTAGES - 1));
    }

    // epilogue
    #pragma unroll
    for (int mt = 0; mt < 4; ++mt) {
        #pragma unroll
        for (int nt = 0; nt < 4; ++nt) {
            int r0 = rowBase + wm + mt * 16 + g;
            int r1 = r0 + 8;
            int c  = colBase + wn + nt * 8 + 2 * tig;
            float v0 = acc[mt][nt][0], v1 = acc[mt][nt][1];
            float v2 = acc[mt][nt][2], v3 = acc[mt][nt][3];
            if (HAS_BIAS) {
                float2 bv = *(const float2*)&bias[c];
                v0 += bv.x; v1 += bv.y; v2 += bv.x; v3 += bv.y;
            }
            if (DO_SILU) {
                v0 = v0 / (1.f + __expf(-v0));
                v1 = v1 / (1.f + __expf(-v1));
                v2 = v2 / (1.f + __expf(-v2));
                v3 = v3 / (1.f + __expf(-v3));
            }
            if (HAS_RES) {
                float2 rv0 = *(const float2*)&res[(size_t)r0 * N + c];
                float2 rv1 = *(const float2*)&res[(size_t)r1 * N + c];
                v0 += rv0.x; v1 += rv0.y; v2 += rv1.x; v3 += rv1.y;
            }
            if (OUT_HALF) {
                __half* C = (__half*)Cv;
                *(__half2*)(C + (size_t)r0 * N + c) = __floats2half2_rn(v0, v1);
                *(__half2*)(C + (size_t)r1 * N + c) = __floats2half2_rn(v2, v3);
            } else {
                float* C = (float*)Cv;
                float2 p0 = {v0, v1}, p1 = {v2, v3};
                *(float2*)(C + (size_t)r0 * N + c) = p0;
                *(float2*)(C + (size_t)r1 * N + c) = p1;
            }
        }
    }
}

// ---------------------------------------------------------------
// FP16 flash attention v4: P@V A-fragments formed directly from
// S-mma output registers (no Pf smem staging), 2 CTAs/SM.
// grid=(SEQ/128, NHEAD, BATCH), 256 threads.
// ---------------------------------------------------------------
#define QF2_SZ (16 * 264)
#define KVP 68
#define KPU_SZ (16 * KVP)
#define ATTN_SMEM (QF2_SZ * 4 + (2 * KPU_SZ) * 8)   // 34304 B

__global__ __launch_bounds__(256, 2) void attn_kernel(
    const __half* __restrict__ qkv, __half* __restrict__ o)
{
    extern __shared__ __align__(16) uint32_t sm2[];
    uint32_t* Qf = sm2;                     // [16][264]
    uint2*    Kp = (uint2*)(Qf + QF2_SZ);   // [16][KVP]
    uint2*    Vp = Kp + KPU_SZ;

    const int tid  = threadIdx.x;
    const int lane = tid & 31, warp = tid >> 5;
    const int g = lane >> 2, tig = lane & 3;

    const int qb = blockIdx.x, h = blockIdx.y, b = blockIdx.z;
    const size_t tokbase = (size_t)b * SEQ;
    const int qrow0 = qb * 128;
    const int qoff = h * HDIM;
    const int koff = DIM + h * HDIM;
    const int voff = 2 * DIM + h * HDIM;

    // ---- stage Q (A-frag pack) ----
    {
        int r  = tid >> 1;
        int d0 = (tid & 1) * 32;
        int w_ = r >> 4, g_ = r & 7, rb = (r >> 3) & 1;
        int posb = (w_ * 8 + g_) * 4 + rb;
        const __half* src = qkv + (tokbase + qrow0 + r) * (size_t)(3 * DIM) + qoff + d0;
        #pragma unroll
        for (int u = 0; u < 4; ++u) {
            uint4 ch = *(const uint4*)(src + u * 8);
            uint32_t w4[4] = {ch.x, ch.y, ch.z, ch.w};
            #pragma unroll
            for (int j = 0; j < 4; ++j) {
                int m = ((d0 + u * 8) >> 1) + j;
                int kb = m >> 3, mm = m & 7;
                int tg = mm & 3, slot = mm >> 2;
                Qf[(kb * 4 + tg) * 264 + posb + slot * 2] = w4[j];
            }
        }
    }

    float m_i[2], l_i[2], oa[8][4];
    m_i[0] = m_i[1] = -1e30f;
    l_i[0] = l_i[1] = 0.f;
    #pragma unroll
    for (int nt = 0; nt < 8; ++nt)
        #pragma unroll
        for (int q = 0; q < 4; ++q) oa[nt][q] = 0.f;

    const int wg4 = (warp * 8 + g) * 4;

    for (int t = 0; t < SEQ / 64; ++t) {
        __syncthreads();
        // ---- stage K ----
        {
            int r  = tid >> 2;
            int d0 = (tid & 3) * 16;
            uint32_t* Kpw = (uint32_t*)Kp;
            const __half* ksrc = qkv + (tokbase + t * 64 + r) * (size_t)(3 * DIM) + koff + d0;
            #pragma unroll
            for (int u = 0; u < 2; ++u) {
                uint4 ch = *(const uint4*)(ksrc + u * 8);
                uint32_t w4[4] = {ch.x, ch.y, ch.z, ch.w};
                #pragma unroll
                for (int j = 0; j < 4; ++j) {
                    int m = ((d0 + u * 8) >> 1) + j;
                    int kb = m >> 3, mm = m & 7;
                    int tg = mm & 3, slot = mm >> 2;
                    Kpw[(((kb * 4 + tg) * KVP) + r) * 2 + slot] = w4[j];
                }
            }
        }
        // ---- stage V ----
        {
            int kp = tid & 31;
            int d0 = (tid >> 5) * 8;
            int kb = kp >> 3, mm = kp & 7;
            int tg = mm & 3, slot = mm >> 2;
            uint32_t* Vpw = (uint32_t*)Vp;
            const __half* v0p = qkv + (tokbase + t * 64 + 2 * kp)     * (size_t)(3 * DIM) + voff + d0;
            const __half* v1p = qkv + (tokbase + t * 64 + 2 * kp + 1) * (size_t)(3 * DIM) + voff + d0;
            uint4 c0 = *(const uint4*)v0p;
            uint4 c1 = *(const uint4*)v1p;
            const __half2* h0 = (const __half2*)&c0;
            const __half2* h1 = (const __half2*)&c1;
            #pragma unroll
            for (int j = 0; j < 4; ++j) {
                __half2 lo = __halves2half2(__low2half(h0[j]),  __low2half(h1[j]));
                __half2 hi = __halves2half2(__high2half(h0[j]), __high2half(h1[j]));
                int d = d0 + 2 * j;
                Vpw[(((kb * 4 + tg) * KVP) + d)     * 2 + slot] = h2_bits(lo);
                Vpw[(((kb * 4 + tg) * KVP) + d + 1) * 2 + slot] = h2_bits(hi);
            }
        }
        __syncthreads();

        // ---- S = Q @ K^T ----
        float s[8][4];
        #pragma unroll
        for (int nt = 0; nt < 8; ++nt)
            #pragma unroll
            for (int q = 0; q < 4; ++q) s[nt][q] = 0.f;
        #pragma unroll
        for (int kb = 0; kb < 4; ++kb) {
            uint4 aq = *(uint4*)&Qf[(kb * 4 + tig) * 264 + wg4];
            #pragma unroll
            for (int nt = 0; nt < 8; ++nt) {
                uint2 bv = Kp[(kb * 4 + tig) * KVP + nt * 8 + g];
                mma_f16(s[nt][0], s[nt][1], s[nt][2], s[nt][3],
                        aq.x, aq.y, aq.z, aq.w, bv.x, bv.y);
            }
        }

        // ---- online softmax ----
        const float scale = 0.125f;
        float mx0 = -1e30f, mx1 = -1e30f;
        #pragma unroll
        for (int nt = 0; nt < 8; ++nt) {
            s[nt][0] *= scale; s[nt][1] *= scale;
            s[nt][2] *= scale; s[nt][3] *= scale;
            mx0 = fmaxf(mx0, fmaxf(s[nt][0], s[nt][1]));
            mx1 = fmaxf(mx1, fmaxf(s[nt][2], s[nt][3]));
        }
        #pragma unroll
        for (int off = 1; off <= 2; off <<= 1) {
            mx0 = fmaxf(mx0, __shfl_xor_sync(0xffffffffu, mx0, off));
            mx1 = fmaxf(mx1, __shfl_xor_sync(0xffffffffu, mx1, off));
        }
        float mn0 = fmaxf(m_i[0], mx0), mn1 = fmaxf(m_i[1], mx1);
        float al0 = __expf(m_i[0] - mn0), al1 = __expf(m_i[1] - mn1);
        float rs0 = 0.f, rs1 = 0.f;
        #pragma unroll
        for (int nt = 0; nt < 8; ++nt) {
            s[nt][0] = __expf(s[nt][0] - mn0);
            s[nt][1] = __expf(s[nt][1] - mn0);
            s[nt][2] = __expf(s[nt][2] - mn1);
            s[nt][3] = __expf(s[nt][3] - mn1);
            rs0 += s[nt][0] + s[nt][1];
            rs1 += s[nt][2] + s[nt][3];
        }
        #pragma unroll
        for (int off = 1; off <= 2; off <<= 1) {
            rs0 += __shfl_xor_sync(0xffffffffu, rs0, off);
            rs1 += __shfl_xor_sync(0xffffffffu, rs1, off);
        }
        l_i[0] = l_i[0] * al0 + rs0;
        l_i[1] = l_i[1] * al1 + rs1;
        m_i[0] = mn0; m_i[1] = mn1;
        #pragma unroll
        for (int nt = 0; nt < 8; ++nt) {
            oa[nt][0] *= al0; oa[nt][1] *= al0;
            oa[nt][2] *= al1; oa[nt][3] *= al1;
        }

        // ---- convert P to half2 A-fragments directly in registers ----
        uint32_t pa[4][4];
        #pragma unroll
        for (int kb = 0; kb < 4; ++kb) {
            pa[kb][0] = h2_bits(__floats2half2_rn(s[2*kb][0],   s[2*kb][1]));
            pa[kb][1] = h2_bits(__floats2half2_rn(s[2*kb][2],   s[2*kb][3]));
            pa[kb][2] = h2_bits(__floats2half2_rn(s[2*kb+1][0], s[2*kb+1][1]));
            pa[kb][3] = h2_bits(__floats2half2_rn(s[2*kb+1][2], s[2*kb+1][3]));
        }

        // ---- O += P @ V ----
        #pragma unroll
        for (int kb = 0; kb < 4; ++kb) {
            #pragma unroll
            for (int nt = 0; nt < 8; ++nt) {
                uint2 bv = Vp[(kb * 4 + tig) * KVP + nt * 8 + g];
                mma_f16(oa[nt][0], oa[nt][1], oa[nt][2], oa[nt][3],
                        pa[kb][0], pa[kb][1], pa[kb][2], pa[kb][3],
                        bv.x, bv.y);
            }
        }
    }

    // ---- write O (half) ----
    float inv0 = 1.f / l_i[0], inv1 = 1.f / l_i[1];
    size_t tok0 = tokbase + qrow0 + warp * 16 + g;
    size_t tok1 = tok0 + 8;
    #pragma unroll
    for (int nt = 0; nt < 8; ++nt) {
        int c = qoff + nt * 8 + 2 * tig;
        *(__half2*)(o + tok0 * DIM + c) = __floats2half2_rn(oa[nt][0] * inv0, oa[nt][1] * inv0);
        *(__half2*)(o + tok1 * DIM + c) = __floats2half2_rn(oa[nt][2] * inv1, oa[nt][3] * inv1);
    }
}

// ---------------------------------------------------------------
extern "C" void kernel_launch(void* const* d_in, const int* in_sizes, int n_in,
                              void* d_out, int out_size)
{
    const float* x     = (const float*)d_in[0];
    const float* n1w   = (const float*)d_in[1];
    const float* qkvw  = (const float*)d_in[2];
    const float* projw = (const float*)d_in[3];
    const float* projb = (const float*)d_in[4];
    const float* n2w   = (const float*)d_in[5];
    const float* fc1w  = (const float*)d_in[6];
    const float* fc1b  = (const float*)d_in[7];
    const float* fc2w  = (const float*)d_in[8];
    const float* fc2b  = (const float*)d_in[9];
    float* out = (float*)d_out;

    __half *h, *qkv, *o, *m1;
    __half2 *qkvwP, *projwP, *fc1wP, *fc2wP;
    cudaGetSymbolAddress((void**)&h,      g_h);
    cudaGetSymbolAddress((void**)&qkv,    g_qkv);
    cudaGetSymbolAddress((void**)&o,      g_o);
    cudaGetSymbolAddress((void**)&m1,     g_m1);
    cudaGetSymbolAddress((void**)&qkvwP,  g_qkvwP);
    cudaGetSymbolAddress((void**)&projwP, g_projwP);
    cudaGetSymbolAddress((void**)&fc1wP,  g_fc1wP);
    cudaGetSymbolAddress((void**)&fc2wP,  g_fc2wP);

    static bool attr_done = false;
    if (!attr_done) {
        cudaFuncSetAttribute(gemm16_kernel<true, false, false, false>,
                             cudaFuncAttributeMaxDynamicSharedMemorySize, GEMM_SMEM);
        cudaFuncSetAttribute(gemm16_kernel<false, true, false, true>,
                             cudaFuncAttributeMaxDynamicSharedMemorySize, GEMM_SMEM);
        cudaFuncSetAttribute(gemm16_kernel<true, true, true, false>,
                             cudaFuncAttributeMaxDynamicSharedMemorySize, GEMM_SMEM);
        cudaFuncSetAttribute(attn_kernel,
                             cudaFuncAttributeMaxDynamicSharedMemorySize, ATTN_SMEM);
        attr_done = true;
    }

    // 0) convert weights to pair-interleaved half
    convw_kernel<<<dim3(3 * DIM / 256, DIM / 2), 256>>>(qkvw, qkvwP, 3 * DIM);
    convw_kernel<<<dim3(DIM / 256, DIM / 2),     256>>>(projw, projwP, DIM);
    convw_kernel<<<dim3(MLPD / 256, DIM / 2),    256>>>(fc1w, fc1wP, MLPD);
    convw_kernel<<<dim3(DIM / 256, MLPD / 2),    256>>>(fc2w, fc2wP, DIM);

    // 1) h = rmsnorm(x, norm1_w)  [half]
    rmsnorm_kernel<<<MTOK, 256>>>(x, n1w, h);
    // 2) qkv = h @ qkv_w  [half]
    gemm16_kernel<true, false, false, false>
        <<<dim3(3 * DIM / 128, MTOK / 128), 256, GEMM_SMEM>>>(
        h, qkvwP, qkv, nullptr, nullptr, 3 * DIM, DIM);
    // 3) attention -> o  [half]
    attn_kernel<<<dim3(SEQ / 128, NHEAD, BATCH), 256, ATTN_SMEM>>>(qkv, o);
    // 4) out = x + o @ proj_w + proj_b  [fp32]
    gemm16_kernel<false, true, false, true>
        <<<dim3(DIM / 128, MTOK / 128), 256, GEMM_SMEM>>>(
        o, projwP, out, projb, x, DIM, DIM);
    // 5) h = rmsnorm(out, norm2_w)  [half]
    rmsnorm_kernel<<<MTOK, 256>>>(out, n2w, h);
    // 6) m1 = silu(h @ fc1_w + fc1_b)  [half]
    gemm16_kernel<true, true, true, false>
        <<<dim3(MLPD / 128, MTOK / 128), 256, GEMM_SMEM>>>(
        h, fc1wP, m1, fc1b, nullptr, MLPD, DIM);
    // 7) out = out + m1 @ fc2_w + fc2_b  [fp32]
    gemm16_kernel<false, true, false, true>
        <<<dim3(DIM / 128, MTOK / 128), 256, GEMM_SMEM>>>(
        m1, fc2wP, out, fc2b, out, DIM, MLPD);
}

// round 17
// speedup vs baseline: 1.0623x; 1.0067x over previous
#include <cuda_runtime.h>
#include <cuda_fp16.h>
#include <math.h>
#include <stdint.h>

// Problem constants
#define BATCH 4
#define SEQ   2048
#define DIM   1024
#define NHEAD 16
#define HDIM  64
#define MLPD  4096
#define MTOK  (BATCH*SEQ)   // 8192 tokens

// -------- scratch (device globals; no allocation allowed) --------
__device__ __align__(16) __half g_h  [(size_t)MTOK * DIM];
__device__ __align__(16) __half g_qkv[(size_t)MTOK * 3 * DIM];
__device__ __align__(16) __half g_o  [(size_t)MTOK * DIM];
__device__ __align__(16) __half g_m1 [(size_t)MTOK * MLPD];
// B-fragment-packed weights: [K/16][4][N] uint2
// u.x = half2(w[16kb+2t][n],  w[16kb+2t+1][n])
// u.y = half2(w[16kb+2t+8][n],w[16kb+2t+9][n])
__device__ __align__(16) uint2 g_qkvwP [(size_t)DIM  * 3 * DIM / 4];
__device__ __align__(16) uint2 g_projwP[(size_t)DIM  * DIM / 4];
__device__ __align__(16) uint2 g_fc1wP [(size_t)DIM  * MLPD / 4];
__device__ __align__(16) uint2 g_fc2wP [(size_t)MLPD * DIM / 4];

// ---------------------------------------------------------------
// helpers
// ---------------------------------------------------------------
__device__ __forceinline__ uint32_t h2_bits(__half2 h) {
    return *reinterpret_cast<uint32_t*>(&h);
}
__device__ __forceinline__ void mma_f16(
    float& d0, float& d1, float& d2, float& d3,
    uint32_t a0, uint32_t a1, uint32_t a2, uint32_t a3,
    uint32_t b0, uint32_t b1)
{
    asm volatile(
        "mma.sync.aligned.m16n8k16.row.col.f32.f16.f16.f32 "
        "{%0,%1,%2,%3}, {%4,%5,%6,%7}, {%8,%9}, {%0,%1,%2,%3};\n"
        : "+f"(d0), "+f"(d1), "+f"(d2), "+f"(d3)
        : "r"(a0), "r"(a1), "r"(a2), "r"(a3), "r"(b0), "r"(b1));
}
__device__ __forceinline__ void ldsm_x4(
    uint32_t& r0, uint32_t& r1, uint32_t& r2, uint32_t& r3, uint32_t addr)
{
    asm volatile("ldmatrix.sync.aligned.m8n8.x4.shared.b16 {%0,%1,%2,%3}, [%4];"
                 : "=r"(r0), "=r"(r1), "=r"(r2), "=r"(r3) : "r"(addr));
}
__device__ __forceinline__ void cp16(uint32_t smem_dst, const void* gsrc) {
    asm volatile("cp.async.cg.shared.global [%0], [%1], 16;\n"
                 :: "r"(smem_dst), "l"(gsrc));
}
__device__ __forceinline__ void cp_commit() {
    asm volatile("cp.async.commit_group;\n");
}
__device__ __forceinline__ void cp_wait2() {
    asm volatile("cp.async.wait_group 2;\n");
}

// ---------------------------------------------------------------
// Weight convert: fp32 W[K][N] -> B-fragment-packed uint2 [K/16][4][N]
// ---------------------------------------------------------------
__global__ __launch_bounds__(256) void convw_kernel(
    const float* __restrict__ in, uint2* __restrict__ out, int N)
{
    int n  = blockIdx.x * 256 + threadIdx.x;
    int kb = blockIdx.y;
    int t  = blockIdx.z;
    int k0 = kb * 16 + 2 * t;
    float a0 = in[(size_t)(k0)     * N + n];
    float a1 = in[(size_t)(k0 + 1) * N + n];
    float b0 = in[(size_t)(k0 + 8) * N + n];
    float b1 = in[(size_t)(k0 + 9) * N + n];
    uint2 u;
    u.x = h2_bits(__floats2half2_rn(a0, a1));
    u.y = h2_bits(__floats2half2_rn(b0, b1));
    out[((size_t)kb * 4 + t) * N + n] = u;
}

// ---------------------------------------------------------------
// RMSNorm: fp32 in -> half out
// ---------------------------------------------------------------
__global__ __launch_bounds__(256) void rmsnorm_kernel(
    const float* __restrict__ x, const float* __restrict__ w, __half* __restrict__ y)
{
    int row = blockIdx.x;
    const float4* xr = (const float4*)(x + (size_t)row * DIM);
    float4 v = xr[threadIdx.x];
    float ss = v.x*v.x + v.y*v.y + v.z*v.z + v.w*v.w;
    #pragma unroll
    for (int o = 16; o; o >>= 1) ss += __shfl_xor_sync(0xffffffffu, ss, o);
    __shared__ float red[8];
    if ((threadIdx.x & 31) == 0) red[threadIdx.x >> 5] = ss;
    __syncthreads();
    float tot = 0.f;
    #pragma unroll
    for (int i = 0; i < 8; ++i) tot += red[i];
    float inv = rsqrtf(tot * (1.0f / DIM) + 1e-6f);
    float4 wv = ((const float4*)w)[threadIdx.x];
    __half2 h0 = __floats2half2_rn(v.x * inv * wv.x, v.y * inv * wv.y);
    __half2 h1 = __floats2half2_rn(v.z * inv * wv.z, v.w * inv * wv.w);
    __half2* yo = (__half2*)(y + (size_t)row * DIM) + threadIdx.x * 2;
    yo[0] = h0; yo[1] = h1;
}

// ---------------------------------------------------------------
// FP16 mma GEMM v6: Block 128x128, BK=32, 256 threads,
// warp grid 2x4 (warp tile 64x32), 4-stage cp.async, 2 CTAs/SM.
// A fragments via ldmatrix.x4; B fragments via single LDS.64
// from B-fragment-packed weights.
// ---------------------------------------------------------------
#define AP2 20            // A pitch in half2 (16 + 4 pad); 80B rows, LDSM conflict-free
#define BPU 136           // B pitch in uint2 (128 + 8 pad)
#define ASTG_B (128 * AP2 * 4)   // 10240 B per stage
#define BSTG_B (8 * BPU * 8)     // 8704 B per stage (8 t-rows)
#define GSTAGES 4
#define GEMM_SMEM (GSTAGES * (ASTG_B + BSTG_B))   // 75776 B

template<bool OUT_HALF, bool HAS_BIAS, bool DO_SILU, bool HAS_RES>
__global__ __launch_bounds__(256, 2) void gemm16_kernel(
    const __half* __restrict__ A, const uint2* __restrict__ Bp,
    void* __restrict__ Cv, const float* __restrict__ bias,
    const float* __restrict__ res, int N, int K)
{
    extern __shared__ __align__(16) char dsm[];

    const int tid  = threadIdx.x;
    const int lane = tid & 31, warp = tid >> 5;
    const int wm = (warp & 1) * 64;        // 2 row-groups of 64
    const int wn = (warp >> 1) * 32;       // 4 col-groups of 32
    const int g  = lane >> 2, tig = lane & 3;
    const int rowBase = blockIdx.y * 128;
    const int colBase = blockIdx.x * 128;
    const uint32_t sbase = (uint32_t)__cvta_generic_to_shared(dsm);

    auto ldg = [&](int t, int buf) {
        int k0 = t << 5;
        uint32_t ab = sbase + buf * ASTG_B;
        #pragma unroll
        for (int it = 0; it < 2; ++it) {
            int cid = tid + it * 256;          // 512 chunks (128 rows x 4)
            int row = cid >> 2, ch = cid & 3;
            cp16(ab + (row * AP2 + ch * 4) * 4,
                 A + (size_t)(rowBase + row) * K + k0 + ch * 8);
        }
        uint32_t bb = sbase + GSTAGES * ASTG_B + buf * BSTG_B;
        #pragma unroll
        for (int it = 0; it < 2; ++it) {
            int cid = tid + it * 256;          // 512 chunks (8 rows x 64)
            int row = cid >> 6, ch = cid & 63;
            cp16(bb + row * (BPU * 8) + ch * 16,
                 Bp + (size_t)((k0 >> 4) * 4 + row) * N + colBase + ch * 2);
        }
        cp_commit();
    };

    float acc[4][4][4];
    #pragma unroll
    for (int mt = 0; mt < 4; ++mt)
        #pragma unroll
        for (int nt = 0; nt < 4; ++nt)
            #pragma unroll
            for (int q = 0; q < 4; ++q) acc[mt][nt][q] = 0.f;

    auto compute = [&](int buf) {
        const uint32_t abase = sbase + buf * ASTG_B;
        const uint2* Bb = (const uint2*)(dsm + GSTAGES * ASTG_B + buf * BSTG_B);
        #pragma unroll
        for (int s = 0; s < 2; ++s) {
            uint32_t af[4][4];
            #pragma unroll
            for (int mt = 0; mt < 4; ++mt) {
                uint32_t addr = abase
                    + ((wm + mt * 16 + (lane & 15)) * AP2 + s * 8) * 4
                    + (lane >> 4) * 16;
                ldsm_x4(af[mt][0], af[mt][1], af[mt][2], af[mt][3], addr);
            }
            uint2 bf[4];
            #pragma unroll
            for (int nt = 0; nt < 4; ++nt)
                bf[nt] = Bb[(s * 4 + tig) * BPU + wn + nt * 8 + g];
            #pragma unroll
            for (int mt = 0; mt < 4; ++mt)
                #pragma unroll
                for (int nt = 0; nt < 4; ++nt)
                    mma_f16(acc[mt][nt][0], acc[mt][nt][1],
                            acc[mt][nt][2], acc[mt][nt][3],
                            af[mt][0], af[mt][1], af[mt][2], af[mt][3],
                            bf[nt].x, bf[nt].y);
        }
    };

    const int nk = K >> 5;
    ldg(0, 0);
    ldg(1, 1);
    ldg(2, 2);
    for (int t = 0; t < nk; ++t) {
        cp_wait2();
        __syncthreads();
        if (t + 3 < nk) ldg(t + 3, (t + 3) & (GSTAGES - 1));
        compute(t & (GSTAGES - 1));
    }

    // epilogue
    #pragma unroll
    for (int mt = 0; mt < 4; ++mt) {
        #pragma unroll
        for (int nt = 0; nt < 4; ++nt) {
            int r0 = rowBase + wm + mt * 16 + g;
            int r1 = r0 + 8;
            int c  = colBase + wn + nt * 8 + 2 * tig;
            float v0 = acc[mt][nt][0], v1 = acc[mt][nt][1];
            float v2 = acc[mt][nt][2], v3 = acc[mt][nt][3];
            if (HAS_BIAS) {
                float2 bv = *(const float2*)&bias[c];
                v0 += bv.x; v1 += bv.y; v2 += bv.x; v3 += bv.y;
            }
            if (DO_SILU) {
                v0 = v0 / (1.f + __expf(-v0));
                v1 = v1 / (1.f + __expf(-v1));
                v2 = v2 / (1.f + __expf(-v2));
                v3 = v3 / (1.f + __expf(-v3));
            }
            if (HAS_RES) {
                float2 rv0 = *(const float2*)&res[(size_t)r0 * N + c];
                float2 rv1 = *(const float2*)&res[(size_t)r1 * N + c];
                v0 += rv0.x; v1 += rv0.y; v2 += rv1.x; v3 += rv1.y;
            }
            if (OUT_HALF) {
                __half* C = (__half*)Cv;
                *(__half2*)(C + (size_t)r0 * N + c) = __floats2half2_rn(v0, v1);
                *(__half2*)(C + (size_t)r1 * N + c) = __floats2half2_rn(v2, v3);
            } else {
                float* C = (float*)Cv;
                float2 p0 = {v0, v1}, p1 = {v2, v3};
                *(float2*)(C + (size_t)r0 * N + c) = p0;
                *(float2*)(C + (size_t)r1 * N + c) = p1;
            }
        }
    }
}

// ---------------------------------------------------------------
// FP16 flash attention v4 (R16 winner, unchanged): register-direct
// P@V fragments, 2 CTAs/SM. grid=(SEQ/128, NHEAD, BATCH), 256 thr.
// ---------------------------------------------------------------
#define QF2_SZ (16 * 264)
#define KVP 68
#define KPU_SZ (16 * KVP)
#define ATTN_SMEM (QF2_SZ * 4 + (2 * KPU_SZ) * 8)   // 34304 B

__global__ __launch_bounds__(256, 2) void attn_kernel(
    const __half* __restrict__ qkv, __half* __restrict__ o)
{
    extern __shared__ __align__(16) uint32_t sm2[];
    uint32_t* Qf = sm2;                     // [16][264]
    uint2*    Kp = (uint2*)(Qf + QF2_SZ);   // [16][KVP]
    uint2*    Vp = Kp + KPU_SZ;

    const int tid  = threadIdx.x;
    const int lane = tid & 31, warp = tid >> 5;
    const int g = lane >> 2, tig = lane & 3;

    const int qb = blockIdx.x, h = blockIdx.y, b = blockIdx.z;
    const size_t tokbase = (size_t)b * SEQ;
    const int qrow0 = qb * 128;
    const int qoff = h * HDIM;
    const int koff = DIM + h * HDIM;
    const int voff = 2 * DIM + h * HDIM;

    // ---- stage Q (A-frag pack) ----
    {
        int r  = tid >> 1;
        int d0 = (tid & 1) * 32;
        int w_ = r >> 4, g_ = r & 7, rb = (r >> 3) & 1;
        int posb = (w_ * 8 + g_) * 4 + rb;
        const __half* src = qkv + (tokbase + qrow0 + r) * (size_t)(3 * DIM) + qoff + d0;
        #pragma unroll
        for (int u = 0; u < 4; ++u) {
            uint4 ch = *(const uint4*)(src + u * 8);
            uint32_t w4[4] = {ch.x, ch.y, ch.z, ch.w};
            #pragma unroll
            for (int j = 0; j < 4; ++j) {
                int m = ((d0 + u * 8) >> 1) + j;
                int kb = m >> 3, mm = m & 7;
                int tg = mm & 3, slot = mm >> 2;
                Qf[(kb * 4 + tg) * 264 + posb + slot * 2] = w4[j];
            }
        }
    }

    float m_i[2], l_i[2], oa[8][4];
    m_i[0] = m_i[1] = -1e30f;
    l_i[0] = l_i[1] = 0.f;
    #pragma unroll
    for (int nt = 0; nt < 8; ++nt)
        #pragma unroll
        for (int q = 0; q < 4; ++q) oa[nt][q] = 0.f;

    const int wg4 = (warp * 8 + g) * 4;

    for (int t = 0; t < SEQ / 64; ++t) {
        __syncthreads();
        // ---- stage K ----
        {
            int r  = tid >> 2;
            int d0 = (tid & 3) * 16;
            uint32_t* Kpw = (uint32_t*)Kp;
            const __half* ksrc = qkv + (tokbase + t * 64 + r) * (size_t)(3 * DIM) + koff + d0;
            #pragma unroll
            for (int u = 0; u < 2; ++u) {
                uint4 ch = *(const uint4*)(ksrc + u * 8);
                uint32_t w4[4] = {ch.x, ch.y, ch.z, ch.w};
                #pragma unroll
                for (int j = 0; j < 4; ++j) {
                    int m = ((d0 + u * 8) >> 1) + j;
                    int kb = m >> 3, mm = m & 7;
                    int tg = mm & 3, slot = mm >> 2;
                    Kpw[(((kb * 4 + tg) * KVP) + r) * 2 + slot] = w4[j];
                }
            }
        }
        // ---- stage V ----
        {
            int kp = tid & 31;
            int d0 = (tid >> 5) * 8;
            int kb = kp >> 3, mm = kp & 7;
            int tg = mm & 3, slot = mm >> 2;
            uint32_t* Vpw = (uint32_t*)Vp;
            const __half* v0p = qkv + (tokbase + t * 64 + 2 * kp)     * (size_t)(3 * DIM) + voff + d0;
            const __half* v1p = qkv + (tokbase + t * 64 + 2 * kp + 1) * (size_t)(3 * DIM) + voff + d0;
            uint4 c0 = *(const uint4*)v0p;
            uint4 c1 = *(const uint4*)v1p;
            const __half2* h0 = (const __half2*)&c0;
            const __half2* h1 = (const __half2*)&c1;
            #pragma unroll
            for (int j = 0; j < 4; ++j) {
                __half2 lo = __halves2half2(__low2half(h0[j]),  __low2half(h1[j]));
                __half2 hi = __halves2half2(__high2half(h0[j]), __high2half(h1[j]));
                int d = d0 + 2 * j;
                Vpw[(((kb * 4 + tg) * KVP) + d)     * 2 + slot] = h2_bits(lo);
                Vpw[(((kb * 4 + tg) * KVP) + d + 1) * 2 + slot] = h2_bits(hi);
            }
        }
        __syncthreads();

        // ---- S = Q @ K^T ----
        float s[8][4];
        #pragma unroll
        for (int nt = 0; nt < 8; ++nt)
            #pragma unroll
            for (int q = 0; q < 4; ++q) s[nt][q] = 0.f;
        #pragma unroll
        for (int kb = 0; kb < 4; ++kb) {
            uint4 aq = *(uint4*)&Qf[(kb * 4 + tig) * 264 + wg4];
            #pragma unroll
            for (int nt = 0; nt < 8; ++nt) {
                uint2 bv = Kp[(kb * 4 + tig) * KVP + nt * 8 + g];
                mma_f16(s[nt][0], s[nt][1], s[nt][2], s[nt][3],
                        aq.x, aq.y, aq.z, aq.w, bv.x, bv.y);
            }
        }

        // ---- online softmax ----
        const float scale = 0.125f;
        float mx0 = -1e30f, mx1 = -1e30f;
        #pragma unroll
        for (int nt = 0; nt < 8; ++nt) {
            s[nt][0] *= scale; s[nt][1] *= scale;
            s[nt][2] *= scale; s[nt][3] *= scale;
            mx0 = fmaxf(mx0, fmaxf(s[nt][0], s[nt][1]));
            mx1 = fmaxf(mx1, fmaxf(s[nt][2], s[nt][3]));
        }
        #pragma unroll
        for (int off = 1; off <= 2; off <<= 1) {
            mx0 = fmaxf(mx0, __shfl_xor_sync(0xffffffffu, mx0, off));
            mx1 = fmaxf(mx1, __shfl_xor_sync(0xffffffffu, mx1, off));
        }
        float mn0 = fmaxf(m_i[0], mx0), mn1 = fmaxf(m_i[1], mx1);
        float al0 = __expf(m_i[0] - mn0), al1 = __expf(m_i[1] - mn1);
        float rs0 = 0.f, rs1 = 0.f;
        #pragma unroll
        for (int nt = 0; nt < 8; ++nt) {
            s[nt][0] = __expf(s[nt][0] - mn0);
            s[nt][1] = __expf(s[nt][1] - mn0);
            s[nt][2] = __expf(s[nt][2] - mn1);
            s[nt][3] = __expf(s[nt][3] - mn1);
            rs0 += s[nt][0] + s[nt][1];
            rs1 += s[nt][2] + s[nt][3];
        }
        #pragma unroll
        for (int off = 1; off <= 2; off <<= 1) {
            rs0 += __shfl_xor_sync(0xffffffffu, rs0, off);
            rs1 += __shfl_xor_sync(0xffffffffu, rs1, off);
        }
        l_i[0] = l_i[0] * al0 + rs0;
        l_i[1] = l_i[1] * al1 + rs1;
        m_i[0] = mn0; m_i[1] = mn1;
        #pragma unroll
        for (int nt = 0; nt < 8; ++nt) {
            oa[nt][0] *= al0; oa[nt][1] *= al0;
            oa[nt][2] *= al1; oa[nt][3] *= al1;
        }

        // ---- convert P to half2 A-fragments directly in registers ----
        uint32_t pa[4][4];
        #pragma unroll
        for (int kb = 0; kb < 4; ++kb) {
            pa[kb][0] = h2_bits(__floats2half2_rn(s[2*kb][0],   s[2*kb][1]));
            pa[kb][1] = h2_bits(__floats2half2_rn(s[2*kb][2],   s[2*kb][3]));
            pa[kb][2] = h2_bits(__floats2half2_rn(s[2*kb+1][0], s[2*kb+1][1]));
            pa[kb][3] = h2_bits(__floats2half2_rn(s[2*kb+1][2], s[2*kb+1][3]));
        }

        // ---- O += P @ V ----
        #pragma unroll
        for (int kb = 0; kb < 4; ++kb) {
            #pragma unroll
            for (int nt = 0; nt < 8; ++nt) {
                uint2 bv = Vp[(kb * 4 + tig) * KVP + nt * 8 + g];
                mma_f16(oa[nt][0], oa[nt][1], oa[nt][2], oa[nt][3],
                        pa[kb][0], pa[kb][1], pa[kb][2], pa[kb][3],
                        bv.x, bv.y);
            }
        }
    }

    // ---- write O (half) ----
    float inv0 = 1.f / l_i[0], inv1 = 1.f / l_i[1];
    size_t tok0 = tokbase + qrow0 + warp * 16 + g;
    size_t tok1 = tok0 + 8;
    #pragma unroll
    for (int nt = 0; nt < 8; ++nt) {
        int c = qoff + nt * 8 + 2 * tig;
        *(__half2*)(o + tok0 * DIM + c) = __floats2half2_rn(oa[nt][0] * inv0, oa[nt][1] * inv0);
        *(__half2*)(o + tok1 * DIM + c) = __floats2half2_rn(oa[nt][2] * inv1, oa[nt][3] * inv1);
    }
}

// ---------------------------------------------------------------
extern "C" void kernel_launch(void* const* d_in, const int* in_sizes, int n_in,
                              void* d_out, int out_size)
{
    const float* x     = (const float*)d_in[0];
    const float* n1w   = (const float*)d_in[1];
    const float* qkvw  = (const float*)d_in[2];
    const float* projw = (const float*)d_in[3];
    const float* projb = (const float*)d_in[4];
    const float* n2w   = (const float*)d_in[5];
    const float* fc1w  = (const float*)d_in[6];
    const float* fc1b  = (const float*)d_in[7];
    const float* fc2w  = (const float*)d_in[8];
    const float* fc2b  = (const float*)d_in[9];
    float* out = (float*)d_out;

    __half *h, *qkv, *o, *m1;
    uint2 *qkvwP, *projwP, *fc1wP, *fc2wP;
    cudaGetSymbolAddress((void**)&h,      g_h);
    cudaGetSymbolAddress((void**)&qkv,    g_qkv);
    cudaGetSymbolAddress((void**)&o,      g_o);
    cudaGetSymbolAddress((void**)&m1,     g_m1);
    cudaGetSymbolAddress((void**)&qkvwP,  g_qkvwP);
    cudaGetSymbolAddress((void**)&projwP, g_projwP);
    cudaGetSymbolAddress((void**)&fc1wP,  g_fc1wP);
    cudaGetSymbolAddress((void**)&fc2wP,  g_fc2wP);

    static bool attr_done = false;
    if (!attr_done) {
        cudaFuncSetAttribute(gemm16_kernel<true, false, false, false>,
                             cudaFuncAttributeMaxDynamicSharedMemorySize, GEMM_SMEM);
        cudaFuncSetAttribute(gemm16_kernel<false, true, false, true>,
                             cudaFuncAttributeMaxDynamicSharedMemorySize, GEMM_SMEM);
        cudaFuncSetAttribute(gemm16_kernel<true, true, true, false>,
                             cudaFuncAttributeMaxDynamicSharedMemorySize, GEMM_SMEM);
        cudaFuncSetAttribute(attn_kernel,
                             cudaFuncAttributeMaxDynamicSharedMemorySize, ATTN_SMEM);
        attr_done = true;
    }

    // 0) convert weights to B-fragment-packed layout
    convw_kernel<<<dim3(3 * DIM / 256, DIM / 16, 4), 256>>>(qkvw, qkvwP, 3 * DIM);
    convw_kernel<<<dim3(DIM / 256, DIM / 16, 4),     256>>>(projw, projwP, DIM);
    convw_kernel<<<dim3(MLPD / 256, DIM / 16, 4),    256>>>(fc1w, fc1wP, MLPD);
    convw_kernel<<<dim3(DIM / 256, MLPD / 16, 4),    256>>>(fc2w, fc2wP, DIM);

    // 1) h = rmsnorm(x, norm1_w)  [half]
    rmsnorm_kernel<<<MTOK, 256>>>(x, n1w, h);
    // 2) qkv = h @ qkv_w  [half]
    gemm16_kernel<true, false, false, false>
        <<<dim3(3 * DIM / 128, MTOK / 128), 256, GEMM_SMEM>>>(
        h, qkvwP, qkv, nullptr, nullptr, 3 * DIM, DIM);
    // 3) attention -> o  [half]
    attn_kernel<<<dim3(SEQ / 128, NHEAD, BATCH), 256, ATTN_SMEM>>>(qkv, o);
    // 4) out = x + o @ proj_w + proj_b  [fp32]
    gemm16_kernel<false, true, false, true>
        <<<dim3(DIM / 128, MTOK / 128), 256, GEMM_SMEM>>>(
        o, projwP, out, projb, x, DIM, DIM);
    // 5) h = rmsnorm(out, norm2_w)  [half]
    rmsnorm_kernel<<<MTOK, 256>>>(out, n2w, h);
    // 6) m1 = silu(h @ fc1_w + fc1_b)  [half]
    gemm16_kernel<true, true, true, false>
        <<<dim3(MLPD / 128, MTOK / 128), 256, GEMM_SMEM>>>(
        h, fc1wP, m1, fc1b, nullptr, MLPD, DIM);
    // 7) out = out + m1 @ fc2_w + fc2_b  [fp32]
    gemm16_kernel<false, true, false, true>
        <<<dim3(DIM / 128, MTOK / 128), 256, GEMM_SMEM>>>(
        m1, fc2wP, out, fc2b, out, DIM, MLPD);
}